// round 17
// baseline (speedup 1.0000x reference)
#include <cuda_runtime.h>
#include <math.h>

#define T_   2048
#define BK   64
#define H_   16
#define N_   64
#define TB   (T_*BK)
#define NC   32
#define CH   64

typedef unsigned long long ULL;

// -------- device scratch (static; b-major) --------
__device__ float  g_C  [(size_t)TB*N_];       // 33.5 MB  C[b][t][n]
__device__ float2 g_yD [(size_t)TB*H_];       // (y_local+du, D)[b][t][h]
__device__ float  g_end [NC*BK*H_*N_];        // 8 MB
__device__ float  g_init[NC*BK*H_*N_];        // 8 MB
__device__ float  g_V[64*H_];
__device__ float  g_g0[H_*N_];

__device__ __forceinline__ ULL pack2(float x) {
    ULL r; asm("mov.b64 %0, {%1, %1};" : "=l"(r) : "f"(x)); return r;
}
__device__ __forceinline__ void fma2(ULL& d, ULL a, ULL b) {
    asm("fma.rn.f32x2 %0, %1, %2, %0;" : "+l"(d) : "l"(a), "l"(b));
}
__device__ __forceinline__ void mul2(ULL& d, ULL a, ULL b) {
    asm("mul.rn.f32x2 %0, %1, %2;" : "=l"(d) : "l"(a), "l"(b));
}
__device__ __forceinline__ float2 unpack2(ULL v) {
    float lo, hi;
    asm("mov.b64 {%0, %1}, %2;" : "=f"(lo), "=f"(hi) : "l"(v));
    return make_float2(lo, hi);
}

// smem layout (float offsets), ~101.6 KB -> 2 CTAs/SM
#define OFF_WB  0                       // [64][64]
#define OFF_WC  4096                    // [64][64]
#define OFF_V   8192                    // [64][16]
#define OFF_O   9216                    // [64 t][68]  (scan aliases: sGmid etc.)
#define OFF_RW  (OFF_O + 64*68)         // 13568, [64]
#define OFF_B   (OFF_RW + 64)           // 13632, [64 t][68]
#define OFF_C   (OFF_B + 64*68)         // 17984, [64 t][68]
#define OFF_S   (OFF_C + 64*68)         // 22336, [64 t][16 h]
#define OFF_DEC (OFF_S + 1024)          // 23360, [64 t][16 h]
#define OFF_DU  (OFF_DEC + 1024)        // 24384, [64 t][16 h]
#define MEGA_SMEM ((OFF_DU + 1024) * 4) // 101632 bytes

// ---------------------------------------------------------------------------
__global__ void prep_kernel(const float* __restrict__ W_in,
                            const float* __restrict__ W_out,
                            const float* __restrict__ init_state) {
    int tid = blockIdx.x * blockDim.x + threadIdx.x;
    if (tid < 64 * H_) {
        int o = tid >> 4, h = tid & 15;
        float acc = 0.f;
        #pragma unroll 8
        for (int p = 0; p < 64; p++)
            acc = fmaf(W_in[o*1024 + h*64 + p], W_out[h*64 + p], acc);
        g_V[o*H_ + h] = acc;
    } else if (tid < 64*H_ + H_*N_) {
        int i = tid - 64*H_;
        int h = i >> 6, n = i & 63;
        float acc = 0.f;
        #pragma unroll 8
        for (int p = 0; p < 64; p++)
            acc = fmaf(init_state[(h*64 + p)*64 + n], W_out[h*64 + p], acc);
        g_g0[i] = acc;
    }
}

// ---------------------------------------------------------------------------
// mega: CTA = (b, 64-t chunk), 2 CTAs/SM. GEMM/V-GEMM as R16 (measured-good).
// Scan: intra-CTA split — warps 0-3 scan t=0..31 (heads (w&3)*4..+3), warps
// 4-7 scan t=32..63 in PARALLEL from zero state; after a barrier, warps 4-7
// correct their outputs with g_mid = first half's final states.
// ---------------------------------------------------------------------------
__global__ void __launch_bounds__(256, 2)
mega_kernel(const float* __restrict__ obs,
            const float* __restrict__ reward,
            const float* __restrict__ W_B,
            const float* __restrict__ W_C,
            const float* __restrict__ W_dt,
            const float* __restrict__ dt_bias,
            const float* __restrict__ A_log,
            const float* __restrict__ Dv) {
    extern __shared__ float sm[];
    float* sWB  = sm + OFF_WB;
    float* sWC  = sm + OFF_WC;
    float* sV   = sm + OFF_V;
    float* sO   = sm + OFF_O;
    float* sRw  = sm + OFF_RW;
    float* sB   = sm + OFF_B;
    float* sC   = sm + OFF_C;
    float* sS   = sm + OFF_S;
    float* sDec = sm + OFF_DEC;
    float* sDu  = sm + OFF_DU;
    // scan-phase aliases over dead obs tile
    float* sGmid = sm + OFF_O;             // [16 h][64 n]
    float* sPmid = sm + OFF_O + 1024;      // [16]
    float* sP2   = sm + OFF_O + 1024 + 16; // [16]

    int b = blockIdx.x & 63, c = blockIdx.x >> 6;
    int tid = threadIdx.x;
    int w = tid >> 5, lane = tid & 31;
    size_t bT = (size_t)b * T_;
    int t0c = c * CH;

    // ---- stage weights + V + obs + reward ----
    #pragma unroll
    for (int i = 0; i < 4; i++) {
        ((float4*)sWB)[tid + 256*i] = ((const float4*)W_B)[tid + 256*i];
        ((float4*)sWC)[tid + 256*i] = ((const float4*)W_C)[tid + 256*i];
    }
    ((float4*)sV)[tid] = ((const float4*)g_V)[tid];
    {
        int cc = (tid & 15) * 4;
        #pragma unroll
        for (int i = 0; i < 4; i++) {
            int f  = tid + 256*i;
            int tt = f >> 4;
            float4 v = *(const float4*)(obs + ((size_t)(t0c + tt)*64 + b)*64 + cc);
            *(float4*)&sO[tt*68 + cc] = v;
        }
        if (tid < 64) sRw[tid] = reward[(t0c + tid)*64 + b];
    }
    __syncthreads();

    // ---- main GEMM: B warps 0-3, C warps 4-7; warp tile 32t x 32c ----
    {
        bool isB = (w < 4);
        int wl = isB ? w : w - 4;
        int tbase   = (wl >> 1) * 32;
        int colbase = (wl & 1) * 32;
        int cx = lane & 3;
        int tg = lane >> 2;
        const float* sW = isB ? sWB : sWC;

        ULL acc[4][4];
        #pragma unroll
        for (int i = 0; i < 4; i++)
            #pragma unroll
            for (int j = 0; j < 4; j++) acc[i][j] = 0ull;

        #pragma unroll 2
        for (int k4 = 0; k4 < 16; k4++) {
            float4 av[4];
            #pragma unroll
            for (int i = 0; i < 4; i++)
                av[i] = *(const float4*)&sO[(tbase + tg + 8*i)*68 + k4*4];
            #pragma unroll
            for (int kk = 0; kk < 4; kk++) {
                int k = k4*4 + kk;
                ulonglong2 wA = *(const ulonglong2*)&sW[k*64 + colbase + cx*8];
                ulonglong2 wB = *(const ulonglong2*)&sW[k*64 + colbase + cx*8 + 4];
                #pragma unroll
                for (int i = 0; i < 4; i++) {
                    float a = (kk == 0) ? av[i].x : (kk == 1) ? av[i].y
                            : (kk == 2) ? av[i].z : av[i].w;
                    ULL ap = pack2(a);
                    fma2(acc[i][0], ap, wA.x);
                    fma2(acc[i][1], ap, wA.y);
                    fma2(acc[i][2], ap, wB.x);
                    fma2(acc[i][3], ap, wB.y);
                }
            }
        }

        float* sT = isB ? sB : sC;
        #pragma unroll
        for (int i = 0; i < 4; i++) {
            int t = tbase + tg + 8*i;
            ulonglong2 q0 = make_ulonglong2(acc[i][0], acc[i][1]);
            ulonglong2 q1 = make_ulonglong2(acc[i][2], acc[i][3]);
            *(ulonglong2*)&sT[t*68 + colbase + cx*8]     = q0;
            *(ulonglong2*)&sT[t*68 + colbase + cx*8 + 4] = q1;
            if (!isB) {
                float* gp = g_C + (bT + t0c + t)*64 + colbase + cx*8;
                *(ulonglong2*)(gp)     = q0;
                *(ulonglong2*)(gp + 4) = q1;
            }
        }
    }

    // ---- V-GEMM + sd/du: thread owns (t = tid>>2, heads ho*4..ho*4+3) ----
    {
        int tV = tid >> 2, ho = tid & 3;
        float s0[4] = {0.f, 0.f, 0.f, 0.f};
        #pragma unroll 4
        for (int k = 0; k < 64; k++) {
            float a = sO[tV*68 + k];
            float4 v0 = *(const float4*)&sV[k*16 + ho*4];
            s0[0] = fmaf(a, v0.x, s0[0]); s0[1] = fmaf(a, v0.y, s0[1]);
            s0[2] = fmaf(a, v0.z, s0[2]); s0[3] = fmaf(a, v0.w, s0[3]);
        }
        float4 wd4 = __ldg((const float4*)(W_dt    + ho*4));
        float4 bs4 = __ldg((const float4*)(dt_bias + ho*4));
        float4 al4 = __ldg((const float4*)(A_log   + ho*4));
        float4 dv4 = __ldg((const float4*)(Dv      + ho*4));
        float wd[4] = {wd4.x, wd4.y, wd4.z, wd4.w};
        float bs[4] = {bs4.x, bs4.y, bs4.z, bs4.w};
        float al[4] = {al4.x, al4.y, al4.z, al4.w};
        float dv[4] = {dv4.x, dv4.y, dv4.z, dv4.w};
        float rw = sRw[tV];
        float sv[4], dc[4], du[4];
        #pragma unroll
        for (int j = 0; j < 4; j++) {
            float x  = fmaf(rw, wd[j], bs[j]);
            float dt = fmaxf(x, 0.f) + __logf(1.f + __expf(-fabsf(x)));
            dc[j] = __expf(dt * (-__expf(al[j])));
            sv[j] = dt * s0[j];
            du[j] = dv[j] * s0[j];
        }
        *(float4*)&sS[tV*16 + ho*4]   = make_float4(sv[0], sv[1], sv[2], sv[3]);
        *(float4*)&sDec[tV*16 + ho*4] = make_float4(dc[0], dc[1], dc[2], dc[3]);
        *(float4*)&sDu[tV*16 + ho*4]  = make_float4(du[0], du[1], du[2], du[3]);
    }
    __syncthreads();

    // ---- scan: split halves across all 8 warps ----
    {
        int hf   = w >> 2;             // 0: t=0..31, 1: t=32..63
        int hg   = w & 3;              // head group (4 heads)
        int toff = hf * 32;
        int n0   = 2*lane;
        int myj  = lane >> 3;
        int myq  = lane & 7;
        int hOwn = hg*4 + myj;

        ULL gA = 0ull, gB2 = 0ull, gC2 = 0ull, gD = 0ull;
        float Dcar = 1.f;
        float yw[4], Dw[4];

        for (int win = 0; win < 4; win++) {
            float yv[32];
            float Dl = 1.f;
            #pragma unroll
            for (int q = 0; q < 8; q++) {
                int t = toff + win*8 + q;
                ULL bv = *(const ULL*)&sB[t*68 + n0];
                ULL cv = *(const ULL*)&sC[t*68 + n0];
                float4 s4 = *(const float4*)&sS[t*16 + hg*4];
                float4 d4 = *(const float4*)&sDec[t*16 + hg*4];
                ULL u0, u1, u2, u3;
                mul2(u0, pack2(s4.x), bv); fma2(u0, gA,  pack2(d4.x)); gA  = u0;
                mul2(u1, pack2(s4.y), bv); fma2(u1, gB2, pack2(d4.y)); gB2 = u1;
                mul2(u2, pack2(s4.z), bv); fma2(u2, gC2, pack2(d4.z)); gC2 = u2;
                mul2(u3, pack2(s4.w), bv); fma2(u3, gD,  pack2(d4.w)); gD  = u3;
                ULL y0, y1, y2, y3;
                mul2(y0, gA,  cv); mul2(y1, gB2, cv);
                mul2(y2, gC2, cv); mul2(y3, gD,  cv);
                float2 f0 = unpack2(y0), f1 = unpack2(y1);
                float2 f2 = unpack2(y2), f3 = unpack2(y3);
                yv[q]      = f0.x + f0.y;
                yv[8 + q]  = f1.x + f1.y;
                yv[16 + q] = f2.x + f2.y;
                yv[24 + q] = f3.x + f3.y;
                float dOwn = sDec[t*16 + hOwn];
                if (q <= myq) Dl *= dOwn;
            }
            #pragma unroll
            for (int s = 16; s >= 1; s >>= 1) {
                bool hi = (lane & s) != 0;
                #pragma unroll
                for (int j = 0; j < s; j++) {
                    float snd = hi ? yv[j] : yv[j + s];
                    float rcv = __shfl_xor_sync(0xffffffffu, snd, s);
                    yv[j] = (hi ? yv[j + s] : yv[j]) + rcv;
                }
            }
            int t = toff + win*8 + myq;
            float du = sDu[t*16 + hOwn];
            float Dcur = Dcar * Dl;
            if (hf == 0) {
                g_yD[(bT + t0c + t)*16 + hOwn] = make_float2(yv[0] + du, Dcur);
            } else {
                yw[win] = yv[0] + du;
                Dw[win] = Dcur;
            }
            float Dfull = __shfl_sync(0xffffffffu, Dl, (lane & 24) | 7);
            Dcar *= Dfull;
        }

        if (hf == 0) {
            // publish mid states + first-half total decay
            *(float2*)&sGmid[(hg*4+0)*64 + n0] = unpack2(gA);
            *(float2*)&sGmid[(hg*4+1)*64 + n0] = unpack2(gB2);
            *(float2*)&sGmid[(hg*4+2)*64 + n0] = unpack2(gC2);
            *(float2*)&sGmid[(hg*4+3)*64 + n0] = unpack2(gD);
            if ((lane & 7) == 7) sPmid[hOwn] = Dcar;
        } else {
            if ((lane & 7) == 7) sP2[hOwn] = Dcar;
        }
        __syncthreads();

        if (hf == 1) {
            ULL gm0 = *(const ULL*)&sGmid[(hg*4+0)*64 + n0];
            ULL gm1 = *(const ULL*)&sGmid[(hg*4+1)*64 + n0];
            ULL gm2 = *(const ULL*)&sGmid[(hg*4+2)*64 + n0];
            ULL gm3 = *(const ULL*)&sGmid[(hg*4+3)*64 + n0];
            float pmidOwn = sPmid[hOwn];
            // fix chunk-final states: g_end = g_local2 + P2tot[h]*g_mid[h]
            fma2(gA,  pack2(sP2[hg*4+0]), gm0);
            fma2(gB2, pack2(sP2[hg*4+1]), gm1);
            fma2(gC2, pack2(sP2[hg*4+2]), gm2);
            fma2(gD,  pack2(sP2[hg*4+3]), gm3);

            // correction pass: y[t] += Dpre2[t,h] * (g_mid[h] . C[t])
            for (int win = 0; win < 4; win++) {
                float yv[32];
                #pragma unroll
                for (int q = 0; q < 8; q++) {
                    int t = 32 + win*8 + q;
                    ULL cv = *(const ULL*)&sC[t*68 + n0];
                    ULL y0, y1, y2, y3;
                    mul2(y0, gm0, cv); mul2(y1, gm1, cv);
                    mul2(y2, gm2, cv); mul2(y3, gm3, cv);
                    float2 f0 = unpack2(y0), f1 = unpack2(y1);
                    float2 f2 = unpack2(y2), f3 = unpack2(y3);
                    yv[q]      = f0.x + f0.y;
                    yv[8 + q]  = f1.x + f1.y;
                    yv[16 + q] = f2.x + f2.y;
                    yv[24 + q] = f3.x + f3.y;
                }
                #pragma unroll
                for (int s = 16; s >= 1; s >>= 1) {
                    bool hi = (lane & s) != 0;
                    #pragma unroll
                    for (int j = 0; j < s; j++) {
                        float snd = hi ? yv[j] : yv[j + s];
                        float rcv = __shfl_xor_sync(0xffffffffu, snd, s);
                        yv[j] = (hi ? yv[j + s] : yv[j]) + rcv;
                    }
                }
                int t = 32 + win*8 + myq;
                g_yD[(bT + t0c + t)*16 + hOwn] =
                    make_float2(fmaf(Dw[win], yv[0], yw[win]), Dw[win] * pmidOwn);
            }

            // chunk-final states (packed n-pairs)
            int e = ((c*64 + b)*16 + hg*4)*64 + n0;
            *(float2*)&g_end[e]       = unpack2(gA);
            *(float2*)&g_end[e + 64]  = unpack2(gB2);
            *(float2*)&g_end[e + 128] = unpack2(gC2);
            *(float2*)&g_end[e + 192] = unpack2(gD);
        }
    }
}

// ---------------------------------------------------------------------------
// scan2: stitch 32 chunk initial states per (b,h). Ring prefetch (depth 4).
// ---------------------------------------------------------------------------
__global__ void scan2_kernel() {
    int chain = blockIdx.x * 8 + (threadIdx.x >> 5);
    int lane  = threadIdx.x & 31;
    int h = chain & 15, b = chain >> 4;

    float g1 = g_g0[h*64 + lane];
    float g2 = g_g0[h*64 + lane + 32];
    int gi0 = ((0*64 + b)*16 + h)*64;
    g_init[gi0 + lane]      = g1;
    g_init[gi0 + lane + 32] = g2;

    float P[NC-1];
    #pragma unroll
    for (int j = 0; j < NC-1; j++)
        P[j] = g_yD[((size_t)b*T_ + (j+1)*CH - 1)*16 + h].y;

    float e1[4], e2[4];
    #pragma unroll
    for (int j = 0; j < 4; j++) {
        int e = ((j*64 + b)*16 + h)*64;
        e1[j] = g_end[e + lane];
        e2[j] = g_end[e + lane + 32];
    }

    #pragma unroll
    for (int c = 1; c < NC; c++) {
        int s = (c-1) & 3;
        g1 = fmaf(g1, P[c-1], e1[s]);
        g2 = fmaf(g2, P[c-1], e2[s]);
        int gio = ((c*64 + b)*16 + h)*64;
        g_init[gio + lane]      = g1;
        g_init[gio + lane + 32] = g2;
        int jn = c + 3;
        if (jn <= NC-2) {
            int e = ((jn*64 + b)*16 + h)*64;
            e1[s] = g_end[e + lane];
            e2[s] = g_end[e + lane + 32];
        }
    }
}

// ---------------------------------------------------------------------------
// scan3: correction + head-sum + output. Block per (b,chunk), 8 warps x 8 t.
// Factored inner loop (w = sum_h D_h*gi packed), software-pipelined loads.
// ---------------------------------------------------------------------------
__global__ void scan3_kernel(float* __restrict__ out, int out_size) {
    int b = blockIdx.x & 63, c = blockIdx.x >> 6;
    int lane = threadIdx.x & 31;
    int w    = threadIdx.x >> 5;
    int n0   = 2*lane;

    ULL gi[16];
    #pragma unroll
    for (int h = 0; h < 16; h++) {
        int giOff = ((c*64 + b)*16 + h)*64;
        gi[h] = *(const ULL*)&g_init[giOff + n0];
    }

    size_t bT = (size_t)b*T_;
    int tbase = c*CH + w*8;

    ULL cv = *(const ULL*)&g_C[(bT + tbase)*64 + n0];
    float2 yD = make_float2(0.f, 0.f);
    if (lane < 16) yD = g_yD[(bT + tbase)*16 + lane];

    #pragma unroll
    for (int q = 0; q < 8; q++) {
        ULL cvn = 0ull;
        float2 yDn = make_float2(0.f, 0.f);
        if (q < 7) {
            size_t rn = bT + tbase + q + 1;
            cvn = *(const ULL*)&g_C[rn*64 + n0];
            if (lane < 16) yDn = g_yD[rn*16 + lane];
        }

        ULL wP = 0ull;
        #pragma unroll
        for (int h = 0; h < 16; h++) {
            float Dh = __shfl_sync(0xffffffffu, yD.y, h);
            fma2(wP, pack2(Dh), gi[h]);
        }
        ULL aP; mul2(aP, wP, cv);
        float2 af = unpack2(aP);
        float acc = yD.x + af.x + af.y;
        acc += __shfl_xor_sync(0xffffffffu, acc, 16);
        acc += __shfl_xor_sync(0xffffffffu, acc, 8);
        acc += __shfl_xor_sync(0xffffffffu, acc, 4);
        acc += __shfl_xor_sync(0xffffffffu, acc, 2);
        acc += __shfl_xor_sync(0xffffffffu, acc, 1);
        if (lane == 0) {
            int idx = (tbase + q)*64 + b;
            for (int j = idx; j < out_size; j += TB) out[j] = acc;
        }
        cv = cvn; yD = yDn;
    }
}

// ---------------------------------------------------------------------------
extern "C" void kernel_launch(void* const* d_in, const int* in_sizes, int n_in,
                              void* d_out, int out_size) {
    const float* obs     = (const float*)d_in[0];
    const float* reward  = (const float*)d_in[1];
    const float* W_in    = (const float*)d_in[2];
    const float* W_B     = (const float*)d_in[3];
    const float* W_C     = (const float*)d_in[4];
    const float* W_dt    = (const float*)d_in[5];
    const float* dt_b    = (const float*)d_in[6];
    const float* A_log   = (const float*)d_in[7];
    const float* Dv      = (const float*)d_in[8];
    const float* W_out   = (const float*)d_in[9];
    const float* init    = (const float*)d_in[10];
    float* out = (float*)d_out;

    cudaFuncSetAttribute(mega_kernel,
                         cudaFuncAttributeMaxDynamicSharedMemorySize, MEGA_SMEM);

    prep_kernel<<<8, 256>>>(W_in, W_out, init);
    mega_kernel<<<BK*NC, 256, MEGA_SMEM>>>(obs, reward, W_B, W_C,
                                           W_dt, dt_b, A_log, Dv);
    scan2_kernel<<<BK*H_/8, 256>>>();
    scan3_kernel<<<BK*NC, 256>>>(out, out_size);
}